// round 3
// baseline (speedup 1.0000x reference)
#include <cuda_runtime.h>

#define C_DIM 272
#define T_DIM 1024
#define BATCH 128

#define BM 64
#define BN 64
#define BK 16
#define TM 4
#define TN 4

// Decoded subject indices (handles both int32 and int64 harness layouts).
__device__ int g_sidx[BATCH];

// subject_idx was requested as int64 in the reference, but JAX downcasts to
// int32 unless x64 is enabled. Detect layout: if the buffer is int64 (LE),
// the high 32-bit word of every entry is 0 (values are 0..15). For an int32
// buffer, the odd words are uniform 0..15, so all-64-zero has p ~= 16^-64.
__global__ void decode_sidx_kernel(const int* __restrict__ raw) {
    __shared__ int is_i32;
    if (threadIdx.x == 0) is_i32 = 0;
    __syncthreads();
    int t = threadIdx.x;
    if (t < 64) {
        if (raw[2 * t + 1] != 0) atomicExch(&is_i32, 1);
    }
    __syncthreads();
    if (t < BATCH) {
        g_sidx[t] = is_i32 ? raw[t] : raw[2 * t];
    }
}

// One CTA computes a 64(out-ch) x 64(time) tile of one sample's GEMM:
// out[b] = W[sidx[b]] (272x272, row-major) @ x[b] (272x1024, row-major).
__global__ __launch_bounds__(256)
void subject_gemm_kernel(const float* __restrict__ x,
                         const float* __restrict__ W,
                         float* __restrict__ out) {
    __shared__ float As[BM][BK + 1];  // +1 pad: conflict-free column reads
    __shared__ float Bs[BK][BN];

    const int b     = blockIdx.z;
    const int oBase = blockIdx.y * BM;
    const int tBase = blockIdx.x * BN;
    const int s     = g_sidx[b];

    const float* __restrict__ Wb = W + (size_t)s * C_DIM * C_DIM;
    const float* __restrict__ xb = x + (size_t)b * C_DIM * T_DIM;
    float* __restrict__ ob       = out + (size_t)b * C_DIM * T_DIM;

    const int tid = threadIdx.x;       // 0..255
    const int tx  = tid & 15;          // time sub-tile
    const int ty  = tid >> 4;          // out-ch sub-tile

    // Global->shared load mapping (one float4 each for A and B)
    const int aRow = tid >> 2;         // 0..63
    const int aCol = (tid & 3) * 4;    // 0,4,8,12
    const int bRow = tid >> 4;         // 0..15
    const int bCol = (tid & 15) * 4;   // 0..60

    const int  oLoad  = oBase + aRow;
    const bool aValid = (oLoad < C_DIM);
    const float* aPtr = Wb + (size_t)oLoad * C_DIM + aCol;        // + k0
    const float* bPtr = xb + (size_t)bRow * T_DIM + tBase + bCol; // + k0*T

    float acc[TM][TN];
#pragma unroll
    for (int i = 0; i < TM; i++)
#pragma unroll
        for (int j = 0; j < TN; j++) acc[i][j] = 0.0f;

    // Prologue: fetch tile k0 = 0
    float4 av = aValid ? *(const float4*)(aPtr)
                       : make_float4(0.f, 0.f, 0.f, 0.f);
    float4 bv = *(const float4*)(bPtr);

    // K = 272 = 17 * BK exactly
    for (int k0 = 0; k0 < C_DIM; k0 += BK) {
        // Commit current tile to shared
        As[aRow][aCol + 0] = av.x;
        As[aRow][aCol + 1] = av.y;
        As[aRow][aCol + 2] = av.z;
        As[aRow][aCol + 3] = av.w;
        *(float4*)&Bs[bRow][bCol] = bv;
        __syncthreads();

        // Prefetch next tile while computing (clamped in-bounds on last iter;
        // result discarded when the loop exits).
        const int kn = (k0 + BK < C_DIM) ? (k0 + BK) : k0;
        av = aValid ? *(const float4*)(aPtr + kn)
                    : make_float4(0.f, 0.f, 0.f, 0.f);
        bv = *(const float4*)(bPtr + (size_t)kn * T_DIM);

#pragma unroll
        for (int k = 0; k < BK; k++) {
            const float a0 = As[ty * 4 + 0][k];
            const float a1 = As[ty * 4 + 1][k];
            const float a2 = As[ty * 4 + 2][k];
            const float a3 = As[ty * 4 + 3][k];
            const float4 bq = *(const float4*)&Bs[k][tx * 4];

            acc[0][0] += a0 * bq.x; acc[0][1] += a0 * bq.y;
            acc[0][2] += a0 * bq.z; acc[0][3] += a0 * bq.w;
            acc[1][0] += a1 * bq.x; acc[1][1] += a1 * bq.y;
            acc[1][2] += a1 * bq.z; acc[1][3] += a1 * bq.w;
            acc[2][0] += a2 * bq.x; acc[2][1] += a2 * bq.y;
            acc[2][2] += a2 * bq.z; acc[2][3] += a2 * bq.w;
            acc[3][0] += a3 * bq.x; acc[3][1] += a3 * bq.y;
            acc[3][2] += a3 * bq.z; acc[3][3] += a3 * bq.w;
        }
        __syncthreads();
    }

#pragma unroll
    for (int i = 0; i < TM; i++) {
        const int oo = oBase + ty * 4 + i;
        if (oo < C_DIM) {
            *(float4*)&ob[(size_t)oo * T_DIM + tBase + tx * 4] =
                make_float4(acc[i][0], acc[i][1], acc[i][2], acc[i][3]);
        }
    }
}

extern "C" void kernel_launch(void* const* d_in, const int* in_sizes, int n_in,
                              void* d_out, int out_size) {
    const float* x   = (const float*)d_in[0];
    const int*   idx = (const int*)d_in[1];   // raw words; width auto-detected
    const float* W   = (const float*)d_in[2];
    float* out       = (float*)d_out;

    decode_sidx_kernel<<<1, 128>>>(idx);

    dim3 grid(T_DIM / BN, (C_DIM + BM - 1) / BM, BATCH);  // (16, 5, 128)
    subject_gemm_kernel<<<grid, 256>>>(x, W, out);
}